// round 15
// baseline (speedup 1.0000x reference)
#include <cuda_runtime.h>
#include <cuda_fp16.h>

#define N_NODES 32768
#define N_EDGES 160000
#define DIM     768
#define N_REL   3
#define H1      4
#define O1      192
#define H2      1
#define O2      768

// ---- mma GEMM tiling: single-product fp16, MT128 x NT256, KC=64 ----
#define MT 128
#define NT 256
#define KC 64
#define NCHUNK (DIM / KC)       // 12
#define NSTAGE 3
#define ST_A 0                  // A: 128 rows x 128B
#define ST_B 16384              // B: 256 rows x 128B
#define STAGE_SZ 49152
#define SMEM_TOTAL (NSTAGE * STAGE_SZ)   // 147456 -> 1 CTA/SM, 16 warps

// ---------------- scratch ----------------
__device__ __align__(16) __half g_xr[(size_t)N_REL * N_NODES * DIM];
__device__ float g_Q [N_REL * N_NODES * H1];
__device__ float g_K [N_REL * N_NODES * H1];
__device__ float g_alpha[N_EDGES * H1];
__device__ float g_Wqk[N_REL * 2 * H1 * DIM];           // TRANSPOSED: [r][j][d]
__device__ int   g_src[N_EDGES], g_dst[N_EDGES], g_et[N_EDGES];
__device__ int   g_deg[N_NODES];
__device__ int   g_off[N_NODES + 1];
__device__ int   g_pos[N_NODES];
__device__ int   g_eperm[N_EDGES];
// row compaction
__device__ int   g_mark[N_REL * N_NODES];
__device__ int   g_pref[N_REL * N_NODES + 1];
__device__ int   g_rows[N_REL * N_NODES];
__device__ int   g_cmap[N_REL * N_NODES];
__device__ int   g_rcnt[N_REL];
__device__ __align__(16) __half g_Ahi[(size_t)N_NODES * DIM];
__device__ __align__(16) __half g_Alo[(size_t)N_NODES * DIM];   // only for h (layer-2 Q/K recon)
__device__ __align__(16) __half g_Bthi[(size_t)N_REL * DIM * DIM];  // [r][n][d]

// ---------------- streams/events (program init; none during capture) ----
struct StreamPack {
    cudaStream_t s2, s3;
    cudaEvent_t evFork, evCSR, evQA1, evG1, evA1, evW2, evJ2;
    StreamPack() {
        cudaStreamCreateWithFlags(&s2, cudaStreamNonBlocking);
        cudaStreamCreateWithFlags(&s3, cudaStreamNonBlocking);
        cudaEventCreateWithFlags(&evFork, cudaEventDisableTiming);
        cudaEventCreateWithFlags(&evCSR,  cudaEventDisableTiming);
        cudaEventCreateWithFlags(&evQA1,  cudaEventDisableTiming);
        cudaEventCreateWithFlags(&evG1,   cudaEventDisableTiming);
        cudaEventCreateWithFlags(&evA1,   cudaEventDisableTiming);
        cudaEventCreateWithFlags(&evW2,   cudaEventDisableTiming);
        cudaEventCreateWithFlags(&evJ2,   cudaEventDisableTiming);
    }
};
static StreamPack g_sp;

// ---------------- PTX helpers ----------------
__device__ __forceinline__ unsigned smem_u32(const void* p) {
    unsigned a;
    asm("{ .reg .u64 t; cvta.to.shared.u64 t, %1; cvt.u32.u64 %0, t; }" : "=r"(a) : "l"(p));
    return a;
}
__device__ __forceinline__ void cp16(unsigned d, const void* s) {
    asm volatile("cp.async.cg.shared.global [%0], [%1], 16;" :: "r"(d), "l"(s));
}
__device__ __forceinline__ unsigned sw128(unsigned o) { return o ^ ((o >> 3) & 0x70); }

__device__ __forceinline__ void ldsm4(unsigned* r, unsigned addr) {
    asm volatile("ldmatrix.sync.aligned.m8n8.x4.shared.b16 {%0,%1,%2,%3}, [%4];"
                 : "=r"(r[0]), "=r"(r[1]), "=r"(r[2]), "=r"(r[3]) : "r"(addr));
}
__device__ __forceinline__ void mma16816(float* c, const unsigned* a, const unsigned* b) {
    asm volatile(
        "mma.sync.aligned.m16n8k16.row.col.f32.f16.f16.f32 "
        "{%0,%1,%2,%3}, {%4,%5,%6,%7}, {%8,%9}, {%0,%1,%2,%3};"
        : "+f"(c[0]), "+f"(c[1]), "+f"(c[2]), "+f"(c[3])
        : "r"(a[0]), "r"(a[1]), "r"(a[2]), "r"(a[3]), "r"(b[0]), "r"(b[1]));
}

// ---------------- edge preprocessing ----------------
__global__ void k_zero_deg() {
    int i = blockIdx.x * blockDim.x + threadIdx.x;
    if (i < N_NODES) g_deg[i] = 0;
}
__global__ void k_prep_edges(const int* __restrict__ ei, const int* __restrict__ et) {
    int e = blockIdx.x * blockDim.x + threadIdx.x;
    if (e >= N_EDGES) return;
    int s = ei[e] & (N_NODES - 1);
    int d = ei[N_EDGES + e] & (N_NODES - 1);
    int t = et[e];
    t = (t < 0) ? 0 : (t >= N_REL ? N_REL - 1 : t);
    g_src[e] = s; g_dst[e] = d; g_et[e] = t;
    atomicAdd(&g_deg[d], 1);
}
__global__ void k_scan() {
    __shared__ int ps[1024];
    int tid = threadIdx.x, base = tid * 32, local[32], s = 0;
#pragma unroll
    for (int j = 0; j < 32; j++) { local[j] = g_deg[base + j]; s += local[j]; }
    ps[tid] = s;
    __syncthreads();
    for (int st = 1; st < 1024; st <<= 1) {
        int v = (tid >= st) ? ps[tid - st] : 0;
        __syncthreads(); ps[tid] += v; __syncthreads();
    }
    int run = ps[tid] - s;
#pragma unroll
    for (int j = 0; j < 32; j++) { g_off[base + j] = run; g_pos[base + j] = run; run += local[j]; }
    if (tid == 1023) g_off[N_NODES] = run;
}
__global__ void k_scatter() {
    int e = blockIdx.x * blockDim.x + threadIdx.x;
    if (e >= N_EDGES) return;
    int p = atomicAdd(&g_pos[g_dst[e]], 1);
    g_eperm[p] = e;
}

// ---------------- row compaction: unique (r, src) ----------------
__global__ void k_zero_mark() {
    int i = blockIdx.x * blockDim.x + threadIdx.x;
    if (i < N_REL * N_NODES) g_mark[i] = 0;
}
__global__ void k_mark() {
    int e = blockIdx.x * blockDim.x + threadIdx.x;
    if (e >= N_EDGES) return;
    g_mark[(g_et[e] << 15) + g_src[e]] = 1;
}
__global__ void k_pscan() {          // 1024 threads, 96 entries each
    __shared__ int ps[1024];
    const int PER = (N_REL * N_NODES) / 1024;   // 96
    int tid = threadIdx.x, base = tid * PER, s = 0;
    for (int j = 0; j < PER; j++) s += g_mark[base + j];
    ps[tid] = s;
    __syncthreads();
    for (int st = 1; st < 1024; st <<= 1) {
        int v = (tid >= st) ? ps[tid - st] : 0;
        __syncthreads(); ps[tid] += v; __syncthreads();
    }
    int run = ps[tid] - s;
    for (int j = 0; j < PER; j++) { g_pref[base + j] = run; run += g_mark[base + j]; }
    if (tid == 1023) g_pref[N_REL * N_NODES] = run;
}
__global__ void k_rowscat() {
    int i = blockIdx.x * blockDim.x + threadIdx.x;
    if (i < N_REL) g_rcnt[i] = g_pref[(i + 1) << 15] - g_pref[i << 15];
    if (i >= N_REL * N_NODES) return;
    if (g_mark[i]) {
        int r = i >> 15, n = i & (N_NODES - 1);
        int local = g_pref[i] - g_pref[r << 15];
        g_rows[(r << 15) + local] = n;
        g_cmap[i] = local;
    }
}

// ---------------- fp16 hi of x ----------------
__global__ void k_splitA(const float4* __restrict__ in) {
    int i = blockIdx.x * blockDim.x + threadIdx.x;
    float4 v = in[i];
    ((__half2*)g_Ahi)[2 * i]     = __half2(__float2half(v.x), __float2half(v.y));
    ((__half2*)g_Ahi)[2 * i + 1] = __half2(__float2half(v.z), __float2half(v.w));
}

// ---------------- transpose W (hi only) -> Bt [r][n][d] ----------------
__global__ void k_splitW(const float* __restrict__ W) {
    __shared__ float tile[32][33];
    int r = blockIdx.z, d0 = blockIdx.y * 32, f0 = blockIdx.x * 32;
    int tx = threadIdx.x, ty = threadIdx.y;
    const float* Wr = W + (size_t)r * DIM * DIM;
#pragma unroll
    for (int j = 0; j < 32; j += 8)
        tile[ty + j][tx] = Wr[(size_t)(d0 + ty + j) * DIM + f0 + tx];
    __syncthreads();
#pragma unroll
    for (int j = 0; j < 32; j += 8) {
        int n = f0 + ty + j, d = d0 + tx;
        g_Bthi[((size_t)r * DIM + n) * DIM + d] = __float2half(tile[tx][ty + j]);
    }
}

// ---------------- Wqk[r][j][d] = (W_r @ [q|k]) transposed ----------------
template <int H>
__global__ void k_wqk(const float* __restrict__ W, const float* __restrict__ q,
                      const float* __restrict__ k) {
    int gw = (blockIdx.x * blockDim.x + threadIdx.x) >> 5;   // (r*768 + d)
    int lane = threadIdx.x & 31;
    if (gw >= N_REL * DIM) return;
    int r = gw / DIM, d = gw % DIM;
    const float* Wrow = W + ((size_t)r * DIM + d) * DIM;
    float acc[2 * H];
#pragma unroll
    for (int j = 0; j < 2 * H; j++) acc[j] = 0.f;
    for (int f = lane; f < DIM; f += 32) {
        float w = Wrow[f];
#pragma unroll
        for (int h = 0; h < H; h++) {
            acc[h]     = fmaf(w, __ldg(&q[f * H + h]), acc[h]);
            acc[H + h] = fmaf(w, __ldg(&k[f * H + h]), acc[H + h]);
        }
    }
#pragma unroll
    for (int j = 0; j < 2 * H; j++)
#pragma unroll
        for (int s = 16; s; s >>= 1) acc[j] += __shfl_xor_sync(0xffffffffu, acc[j], s);
    if (lane == 0) {
#pragma unroll
        for (int j = 0; j < 2 * H; j++)
            g_Wqk[((size_t)r * 2 * H + j) * DIM + d] = acc[j];
    }
}

// ---------------- Q/K: smem-staged Wqk, 2 nodes per warp ----------------
template <int H, bool FROM_H>
__global__ __launch_bounds__(256) void k_qkx(const float4* __restrict__ xin) {
    constexpr int NJ = N_REL * 2 * H;
    extern __shared__ float sW[];
    const float4* sW4 = (const float4*)sW;

    int tid = threadIdx.x, lane = tid & 31, w = tid >> 5;
#pragma unroll 4
    for (int i = tid; i < NJ * (DIM / 4); i += 256)
        ((float4*)sW)[i] = ((const float4*)g_Wqk)[i];
    __syncthreads();

    int n0 = blockIdx.x * 16 + w * 2;
    float accA[NJ], accB[NJ];
#pragma unroll
    for (int j = 0; j < NJ; j++) { accA[j] = 0.f; accB[j] = 0.f; }

#pragma unroll
    for (int i = 0; i < DIM / 128; i++) {
        int c4 = i * 32 + lane;
        float4 xa, xb;
        if (FROM_H) {
            uint2 ha = *(const uint2*)(g_Ahi + (size_t)n0 * DIM + 4 * c4);
            uint2 la = *(const uint2*)(g_Alo + (size_t)n0 * DIM + 4 * c4);
            uint2 hb = *(const uint2*)(g_Ahi + (size_t)(n0 + 1) * DIM + 4 * c4);
            uint2 lb = *(const uint2*)(g_Alo + (size_t)(n0 + 1) * DIM + 4 * c4);
            __half2 ah0 = *reinterpret_cast<__half2*>(&ha.x);
            __half2 ah1 = *reinterpret_cast<__half2*>(&ha.y);
            __half2 al0 = *reinterpret_cast<__half2*>(&la.x);
            __half2 al1 = *reinterpret_cast<__half2*>(&la.y);
            xa = make_float4(__half2float(ah0.x) + __half2float(al0.x),
                             __half2float(ah0.y) + __half2float(al0.y),
                             __half2float(ah1.x) + __half2float(al1.x),
                             __half2float(ah1.y) + __half2float(al1.y));
            __half2 bh0 = *reinterpret_cast<__half2*>(&hb.x);
            __half2 bh1 = *reinterpret_cast<__half2*>(&hb.y);
            __half2 bl0 = *reinterpret_cast<__half2*>(&lb.x);
            __half2 bl1 = *reinterpret_cast<__half2*>(&lb.y);
            xb = make_float4(__half2float(bh0.x) + __half2float(bl0.x),
                             __half2float(bh0.y) + __half2float(bl0.y),
                             __half2float(bh1.x) + __half2float(bl1.x),
                             __half2float(bh1.y) + __half2float(bl1.y));
        } else {
            xa = xin[(size_t)n0 * (DIM / 4) + c4];
            xb = xin[(size_t)(n0 + 1) * (DIM / 4) + c4];
        }
#pragma unroll
        for (int j = 0; j < NJ; j++) {
            float4 wv = sW4[j * (DIM / 4) + c4];
            accA[j] = fmaf(xa.x, wv.x, fmaf(xa.y, wv.y, fmaf(xa.z, wv.z, fmaf(xa.w, wv.w, accA[j]))));
            accB[j] = fmaf(xb.x, wv.x, fmaf(xb.y, wv.y, fmaf(xb.z, wv.z, fmaf(xb.w, wv.w, accB[j]))));
        }
    }
#pragma unroll
    for (int j = 0; j < NJ; j++) {
#pragma unroll
        for (int s = 16; s; s >>= 1) {
            accA[j] += __shfl_xor_sync(0xffffffffu, accA[j], s);
            accB[j] += __shfl_xor_sync(0xffffffffu, accB[j], s);
        }
    }
    if (lane < 2) {
        const float* acc = lane == 0 ? accA : accB;
        int n = n0 + lane;
#pragma unroll
        for (int r = 0; r < N_REL; r++)
#pragma unroll
            for (int h = 0; h < H; h++) {
                g_Q[(r * N_NODES + n) * H + h] = acc[r * 2 * H + h];
                g_K[(r * N_NODES + n) * H + h] = acc[r * 2 * H + H + h];
            }
    }
}

// ---------------- HMMA GEMM (single-product fp16, NT=256, 512 threads) --------------
__device__ __forceinline__ void load_chunk(unsigned stg, int k0, const int* sR,
        const __half* bH, int t) {
#pragma unroll
    for (int p = 0; p < 2; p++) {          // A: 1024 16B units
        int u = p * 512 + t;
        int row = u >> 3, kc = u & 7;
        cp16(stg + ST_A + sw128(row * 128 + kc * 16),
             g_Ahi + (size_t)sR[row] * DIM + k0 + kc * 8);
    }
#pragma unroll
    for (int p = 0; p < 4; p++) {          // B: 2048 16B units (256 rows)
        int u = p * 512 + t;
        int row = u >> 3, kc = u & 7;
        cp16(stg + ST_B + sw128(row * 128 + kc * 16),
             bH + (size_t)row * DIM + k0 + kc * 8);
    }
}

__global__ __launch_bounds__(512, 1) void k_gemm_mma() {
    extern __shared__ char smem[];
    __shared__ int sRows[MT];
    unsigned sb = smem_u32(smem);
    int t = threadIdx.x, wid = t >> 5, lane = t & 31;
    int wm = wid & 1, wn = wid >> 1;            // 2(m) x 8(n) warps; warp tile 64x32
    int nt3 = blockIdx.x % 3, r = blockIdx.x / 3;
    int bm = blockIdx.y * MT, bn = nt3 * NT;

    int cnt = g_rcnt[r];
    if (bm >= cnt) return;
    if (t < MT) sRows[t] = (bm + t < cnt) ? g_rows[(r << 15) + bm + t] : 0;

    const __half* bH = g_Bthi + ((size_t)r * DIM + bn) * DIM;

    float acc[4][4][4];
#pragma unroll
    for (int i = 0; i < 4; i++)
#pragma unroll
        for (int j = 0; j < 4; j++)
#pragma unroll
            for (int k = 0; k < 4; k++) acc[i][j][k] = 0.f;

    unsigned aRowB = (unsigned)(wm * 64 + (lane & 15)) * 128;
    unsigned aColB = (unsigned)(lane >> 4) * 16;
    unsigned bRowB = (unsigned)(wn * 32 + (lane & 7) + ((lane >> 4) << 3)) * 128;
    unsigned bColB = (unsigned)((lane >> 3) & 1) * 16;

    __syncthreads();   // sRows visible to all loaders

#pragma unroll
    for (int s = 0; s < NSTAGE - 1; s++) {
        load_chunk(sb + s * STAGE_SZ, s * KC, sRows, bH, t);
        asm volatile("cp.async.commit_group;" ::: "memory");
    }

    for (int i = 0; i < NCHUNK; i++) {
        asm volatile("cp.async.wait_group %0;" :: "n"(NSTAGE - 2) : "memory");
        __syncthreads();

        if (i + NSTAGE - 1 < NCHUNK) {
            load_chunk(sb + ((i + NSTAGE - 1) % NSTAGE) * STAGE_SZ,
                       (i + NSTAGE - 1) * KC, sRows, bH, t);
        }
        asm volatile("cp.async.commit_group;" ::: "memory");

        unsigned stg = sb + (unsigned)(i % NSTAGE) * STAGE_SZ;
#pragma unroll
        for (int ks = 0; ks < 4; ks++) {
            unsigned bHi[2][4];
#pragma unroll
            for (int nb = 0; nb < 2; nb++)
                ldsm4(bHi[nb], stg + ST_B + sw128(bRowB + nb * 2048 + bColB + ks * 32));
#pragma unroll
            for (int mt = 0; mt < 4; mt++) {
                unsigned aHi[4];
                ldsm4(aHi, stg + ST_A + sw128(aRowB + mt * 2048 + aColB + ks * 32));
#pragma unroll
                for (int nb = 0; nb < 2; nb++)
#pragma unroll
                    for (int half = 0; half < 2; half++) {
                        int nt = nb * 2 + half, rg = half * 2;
                        mma16816(acc[mt][nt], aHi, &bHi[nb][rg]);
                    }
            }
        }
    }

    __half* C = g_xr + ((size_t)r * N_NODES + bm) * DIM + bn;
#pragma unroll
    for (int mt = 0; mt < 4; mt++)
#pragma unroll
        for (int nt = 0; nt < 4; nt++) {
            int row = wm * 64 + mt * 16 + (lane >> 2);
            int col = wn * 32 + nt * 8 + (lane & 3) * 2;
            *(__half2*)(C + (size_t)row * DIM + col) =
                __floats2half2_rn(acc[mt][nt][0], acc[mt][nt][1]);
            *(__half2*)(C + (size_t)(row + 8) * DIM + col) =
                __floats2half2_rn(acc[mt][nt][2], acc[mt][nt][3]);
        }
}

// ---------------- per-edge attention logits ----------------
template <int H>
__global__ void k_alpha() {
    int e = blockIdx.x * blockDim.x + threadIdx.x;
    if (e >= N_EDGES) return;
    int et = g_et[e], s = g_src[e], d = g_dst[e];
    int bq = (et * N_NODES + d) * H;
    int bk = (et * N_NODES + s) * H;
#pragma unroll
    for (int h = 0; h < H; h++) {
        float v = g_Q[bq + h] + g_K[bk + h];
        g_alpha[e * H + h] = (v >= 0.f) ? v : 0.2f * v;
    }
}

// ---------------- per-node segment softmax + aggregation (fp16 xr gather) ------------
template <int H, int OUT, bool ELU, bool SPLIT>
__global__ __launch_bounds__(128) void k_agg(const float* __restrict__ bias,
                                             float* __restrict__ outp) {
    int n = blockIdx.x;
    int off = g_off[n];
    int cnt = g_off[n + 1] - off;

    __shared__ float sm_m[H], sm_rz[H];
    __shared__ int   sm_row[128];
    __shared__ float sm_a[128 * H];

    int tid = threadIdx.x, lane = tid & 31, w = tid >> 5;

    if (w < H) {
        float mx = -3.0e38f;
        for (int i = lane; i < cnt; i += 32) {
            int e = g_eperm[off + i];
            mx = fmaxf(mx, g_alpha[e * H + w]);
        }
#pragma unroll
        for (int s = 16; s; s >>= 1) mx = fmaxf(mx, __shfl_xor_sync(0xffffffffu, mx, s));
        float z = 0.f;
        for (int i = lane; i < cnt; i += 32) {
            int e = g_eperm[off + i];
            z += expf(g_alpha[e * H + w] - mx);
        }
#pragma unroll
        for (int s = 16; s; s >>= 1) z += __shfl_xor_sync(0xffffffffu, z, s);
        if (lane == 0) { sm_m[w] = mx; sm_rz[w] = 1.f / (z + 1e-16f); }
    }
    __syncthreads();

    float acc[3][2] = {{0.f,0.f},{0.f,0.f},{0.f,0.f}};
    int hidx[3];
#pragma unroll
    for (int j = 0; j < 3; j++) hidx[j] = (2 * (tid + j * 128)) / OUT;

    const __half2* xr2 = (const __half2*)g_xr;
    for (int base = 0; base < cnt; base += 128) {
        int c = cnt - base;
        if (c > 128) c = 128;
        if (tid < c) {
            int e = g_eperm[off + base + tid];
            int r = g_et[e];
            sm_row[tid] = (r * N_NODES + g_cmap[(r << 15) + g_src[e]]) * (DIM / 2);
#pragma unroll
            for (int h = 0; h < H; h++)
                sm_a[tid * H + h] = expf(g_alpha[e * H + h] - sm_m[h]) * sm_rz[h];
        }
        __syncthreads();
        for (int i = 0; i < c; i++) {
            const __half2* row = xr2 + sm_row[i];
#pragma unroll
            for (int j = 0; j < 3; j++) {
                float a = sm_a[i * H + hidx[j]];
                __half2 hv = row[tid + j * 128];
                acc[j][0] = fmaf(a, __low2float(hv), acc[j][0]);
                acc[j][1] = fmaf(a, __high2float(hv), acc[j][1]);
            }
        }
        __syncthreads();
    }

    size_t ob = (size_t)n * DIM;
#pragma unroll
    for (int j = 0; j < 3; j++) {
        int cch = 2 * (tid + j * 128);
        float v0 = acc[j][0] + bias[cch];
        float v1 = acc[j][1] + bias[cch + 1];
        if (ELU) {
            v0 = (v0 > 0.f) ? v0 : expm1f(v0);
            v1 = (v1 > 0.f) ? v1 : expm1f(v1);
        }
        if (SPLIT) {
            __half h0 = __float2half(v0), h1 = __float2half(v1);
            g_Ahi[ob + cch]     = h0;
            g_Ahi[ob + cch + 1] = h1;
            g_Alo[ob + cch]     = __float2half(v0 - __half2float(h0));
            g_Alo[ob + cch + 1] = __float2half(v1 - __half2float(h1));
        } else {
            outp[ob + cch]     = v0;
            outp[ob + cch + 1] = v1;
        }
    }
}

// ---------------- launch ----------------
extern "C" void kernel_launch(void* const* d_in, const int* in_sizes, int n_in,
                              void* d_out, int out_size) {
    const float* x  = (const float*)d_in[0];
    const int*   ei = (const int*)d_in[1];
    const int*   et = (const int*)d_in[2];
    const float* W1 = (const float*)d_in[3];
    const float* q1 = (const float*)d_in[4];
    const float* k1 = (const float*)d_in[5];
    const float* b1 = (const float*)d_in[6];
    const float* W2 = (const float*)d_in[7];
    const float* q2 = (const float*)d_in[8];
    const float* k2 = (const float*)d_in[9];
    const float* b2 = (const float*)d_in[10];
    float* out = (float*)d_out;

    const int QK1_SMEM = N_REL * 2 * H1 * DIM * 4;   // 73728
    const int QK2_SMEM = N_REL * 2 * H2 * DIM * 4;   // 18432
    cudaFuncSetAttribute(k_gemm_mma, cudaFuncAttributeMaxDynamicSharedMemorySize, SMEM_TOTAL);
    cudaFuncSetAttribute(k_qkx<H1, false>, cudaFuncAttributeMaxDynamicSharedMemorySize, QK1_SMEM);
    cudaFuncSetAttribute(k_qkx<H2, true>,  cudaFuncAttributeMaxDynamicSharedMemorySize, QK2_SMEM);

    cudaStream_t s2 = g_sp.s2, s3 = g_sp.s3;
    dim3 ggrid(3 * N_REL, N_NODES / MT);             // (9, 256)
    dim3 wgrid(DIM / 32, DIM / 32, N_REL);
    dim3 wblk(32, 8);
    int  ablocks = (N_NODES * DIM / 4) / 256;
    int  rnBlocks = (N_REL * N_NODES + 255) / 256;

    // ---- fork helper streams from the capture-origin stream FIRST ----
    cudaEventRecord(g_sp.evFork, 0);
    cudaStreamWaitEvent(s2, g_sp.evFork, 0);
    cudaStreamWaitEvent(s3, g_sp.evFork, 0);

    // main: GEMM-1 inputs only
    k_splitA<<<ablocks, 256>>>((const float4*)x);                  // 1
    k_splitW<<<wgrid, wblk>>>(W1);                                 // 2

    // s3: Q/K path for layer 1 (independent of main prologue)
    k_wqk<H1><<<(N_REL * DIM) / 8, 256, 0, s3>>>(W1, q1, k1);      // 3
    k_qkx<H1, false><<<N_NODES / 16, 256, QK1_SMEM, s3>>>((const float4*)x);  // 4 (profiled)

    // s2: CSR + row compaction
    k_zero_deg<<<(N_NODES + 255) / 256, 256, 0, s2>>>();
    k_prep_edges<<<(N_EDGES + 255) / 256, 256, 0, s2>>>(ei, et);
    k_scan<<<1, 1024, 0, s2>>>();
    k_scatter<<<(N_EDGES + 255) / 256, 256, 0, s2>>>();
    k_zero_mark<<<rnBlocks, 256, 0, s2>>>();
    k_mark<<<(N_EDGES + 255) / 256, 256, 0, s2>>>();
    k_pscan<<<1, 1024, 0, s2>>>();
    k_rowscat<<<rnBlocks, 256, 0, s2>>>();
    cudaEventRecord(g_sp.evCSR, s2);

    // s3: alpha1 after CSR — hides under gemm1
    cudaStreamWaitEvent(s3, g_sp.evCSR, 0);
    k_alpha<H1><<<(N_EDGES + 255) / 256, 256, 0, s3>>>();
    cudaEventRecord(g_sp.evQA1, s3);

    // main: gemm1
    cudaStreamWaitEvent(0, g_sp.evCSR, 0);
    k_gemm_mma<<<ggrid, 512, SMEM_TOTAL>>>();
    cudaEventRecord(g_sp.evG1, 0);

    // s2: layer-2 weight prep — hides under agg1
    cudaStreamWaitEvent(s2, g_sp.evG1, 0);
    k_splitW<<<wgrid, wblk, 0, s2>>>(W2);
    k_wqk<H2><<<(N_REL * DIM) / 8, 256, 0, s2>>>(W2, q2, k2);
    cudaEventRecord(g_sp.evW2, s2);

    // main: agg1 (needs gemm1 + alpha1)
    cudaStreamWaitEvent(0, g_sp.evQA1, 0);
    k_agg<H1, O1, true, true><<<N_NODES, 128>>>(b1, nullptr);
    cudaEventRecord(g_sp.evA1, 0);

    // s3: qkx2 + alpha2 — hides under gemm2
    cudaStreamWaitEvent(s3, g_sp.evA1, 0);
    cudaStreamWaitEvent(s3, g_sp.evW2, 0);
    k_qkx<H2, true><<<N_NODES / 16, 256, QK2_SMEM, s3>>>(nullptr);
    k_alpha<H2><<<(N_EDGES + 255) / 256, 256, 0, s3>>>();
    cudaEventRecord(g_sp.evJ2, s3);

    // main: gemm2 + agg2
    cudaStreamWaitEvent(0, g_sp.evW2, 0);
    k_gemm_mma<<<ggrid, 512, SMEM_TOTAL>>>();
    cudaStreamWaitEvent(0, g_sp.evJ2, 0);
    k_agg<H2, O2, false, false><<<N_NODES, 128>>>(b2, out);
}

// round 16
// speedup vs baseline: 1.0927x; 1.0927x over previous
#include <cuda_runtime.h>
#include <cuda_fp16.h>

#define N_NODES 32768
#define HALFN   16384
#define N_EDGES 160000
#define DIM     768
#define N_REL   3
#define H1      4
#define O1      192
#define H2      1
#define O2      768

// ---- mma GEMM tiling (round-14 measured-best: NT=128, 2 CTA/SM) ----
#define MT 128
#define NT 128
#define KC 64
#define NCHUNK (DIM / KC)       // 12
#define NSTAGE 3
#define ST_A 0
#define ST_B 16384
#define STAGE_SZ 32768
#define SMEM_TOTAL (NSTAGE * STAGE_SZ)   // 98304 -> 2 CTAs/SM

// ---------------- scratch ----------------
__device__ __align__(16) __half g_xr[(size_t)N_REL * N_NODES * DIM];
__device__ float g_Q [N_REL * N_NODES * H1];
__device__ float g_K [N_REL * N_NODES * H1];
__device__ float g_alpha[N_EDGES * H1];
__device__ float g_Wqk[N_REL * 2 * H1 * DIM];           // TRANSPOSED: [r][j][d]
__device__ int   g_src[N_EDGES], g_dst[N_EDGES], g_et[N_EDGES];
__device__ int   g_deg[N_NODES];
__device__ int   g_off[N_NODES + 1];
__device__ int   g_pos[N_NODES];
__device__ int   g_eperm[N_EDGES];
// row compaction
__device__ int   g_mark[N_REL * N_NODES];
__device__ int   g_pref[N_REL * N_NODES + 1];
__device__ int   g_rows[N_REL * N_NODES];
__device__ int   g_cmap[N_REL * N_NODES];
__device__ int   g_rcnt[N_REL];
__device__ __align__(16) __half g_Ahi[(size_t)N_NODES * DIM];
__device__ __align__(16) __half g_Alo[(size_t)N_NODES * DIM];
__device__ __align__(16) __half g_Bthi[(size_t)N_REL * DIM * DIM];  // [r][n][d]

// ---------------- streams/events (program init; none during capture) ----
struct StreamPack {
    cudaStream_t s2, s3;
    cudaEvent_t evFork, evCSR, evQA1, evG1, evW2, evA1a, evA1b, evJ2;
    StreamPack() {
        cudaStreamCreateWithFlags(&s2, cudaStreamNonBlocking);
        cudaStreamCreateWithFlags(&s3, cudaStreamNonBlocking);
        cudaEventCreateWithFlags(&evFork, cudaEventDisableTiming);
        cudaEventCreateWithFlags(&evCSR,  cudaEventDisableTiming);
        cudaEventCreateWithFlags(&evQA1,  cudaEventDisableTiming);
        cudaEventCreateWithFlags(&evG1,   cudaEventDisableTiming);
        cudaEventCreateWithFlags(&evW2,   cudaEventDisableTiming);
        cudaEventCreateWithFlags(&evA1a,  cudaEventDisableTiming);
        cudaEventCreateWithFlags(&evA1b,  cudaEventDisableTiming);
        cudaEventCreateWithFlags(&evJ2,   cudaEventDisableTiming);
    }
};
static StreamPack g_sp;

// ---------------- PTX helpers ----------------
__device__ __forceinline__ unsigned smem_u32(const void* p) {
    unsigned a;
    asm("{ .reg .u64 t; cvta.to.shared.u64 t, %1; cvt.u32.u64 %0, t; }" : "=r"(a) : "l"(p));
    return a;
}
__device__ __forceinline__ void cp16(unsigned d, const void* s) {
    asm volatile("cp.async.cg.shared.global [%0], [%1], 16;" :: "r"(d), "l"(s));
}
__device__ __forceinline__ unsigned sw128(unsigned o) { return o ^ ((o >> 3) & 0x70); }

__device__ __forceinline__ void ldsm4(unsigned* r, unsigned addr) {
    asm volatile("ldmatrix.sync.aligned.m8n8.x4.shared.b16 {%0,%1,%2,%3}, [%4];"
                 : "=r"(r[0]), "=r"(r[1]), "=r"(r[2]), "=r"(r[3]) : "r"(addr));
}
__device__ __forceinline__ void mma16816(float* c, const unsigned* a, const unsigned* b) {
    asm volatile(
        "mma.sync.aligned.m16n8k16.row.col.f32.f16.f16.f32 "
        "{%0,%1,%2,%3}, {%4,%5,%6,%7}, {%8,%9}, {%0,%1,%2,%3};"
        : "+f"(c[0]), "+f"(c[1]), "+f"(c[2]), "+f"(c[3])
        : "r"(a[0]), "r"(a[1]), "r"(a[2]), "r"(a[3]), "r"(b[0]), "r"(b[1]));
}

// ---------------- fused edge preprocessing ----------------
__global__ void k_zero2() {
    int i = blockIdx.x * blockDim.x + threadIdx.x;
    if (i < N_REL * N_NODES) g_mark[i] = 0;
    if (i < N_NODES) g_deg[i] = 0;
}
__global__ void k_prep2(const int* __restrict__ ei, const int* __restrict__ et) {
    int e = blockIdx.x * blockDim.x + threadIdx.x;
    if (e >= N_EDGES) return;
    int s = ei[e] & (N_NODES - 1);
    int d = ei[N_EDGES + e] & (N_NODES - 1);
    int t = et[e];
    t = (t < 0) ? 0 : (t >= N_REL ? N_REL - 1 : t);
    g_src[e] = s; g_dst[e] = d; g_et[e] = t;
    atomicAdd(&g_deg[d], 1);
    g_mark[(t << 15) + s] = 1;
}
__global__ void k_scan2() {
    __shared__ int ps[1024];
    int tid = threadIdx.x;
    if (blockIdx.x == 0) {                   // deg -> off/pos scan
        int base = tid * 32, local[32], s = 0;
#pragma unroll
        for (int j = 0; j < 32; j++) { local[j] = g_deg[base + j]; s += local[j]; }
        ps[tid] = s;
        __syncthreads();
        for (int st = 1; st < 1024; st <<= 1) {
            int v = (tid >= st) ? ps[tid - st] : 0;
            __syncthreads(); ps[tid] += v; __syncthreads();
        }
        int run = ps[tid] - s;
#pragma unroll
        for (int j = 0; j < 32; j++) { g_off[base + j] = run; g_pos[base + j] = run; run += local[j]; }
        if (tid == 1023) g_off[N_NODES] = run;
    } else {                                 // mark -> pref scan
        const int PER = (N_REL * N_NODES) / 1024;   // 96
        int base = tid * PER, s = 0;
        for (int j = 0; j < PER; j++) s += g_mark[base + j];
        ps[tid] = s;
        __syncthreads();
        for (int st = 1; st < 1024; st <<= 1) {
            int v = (tid >= st) ? ps[tid - st] : 0;
            __syncthreads(); ps[tid] += v; __syncthreads();
        }
        int run = ps[tid] - s;
        for (int j = 0; j < PER; j++) { g_pref[base + j] = run; run += g_mark[base + j]; }
        if (tid == 1023) g_pref[N_REL * N_NODES] = run;
    }
}
#define SCAT_BLKS ((N_EDGES + 255) / 256)                      // 625
#define RSC_BLKS  ((N_REL * N_NODES + 255) / 256)              // 384
__global__ void k_scat2() {
    int b = blockIdx.x, tid = threadIdx.x;
    if (b < SCAT_BLKS) {
        int e = b * 256 + tid;
        if (e >= N_EDGES) return;
        int p = atomicAdd(&g_pos[g_dst[e]], 1);
        g_eperm[p] = e;
    } else {
        int i = (b - SCAT_BLKS) * 256 + tid;
        if (i < N_REL) g_rcnt[i] = g_pref[(i + 1) << 15] - g_pref[i << 15];
        if (i >= N_REL * N_NODES) return;
        if (g_mark[i]) {
            int r = i >> 15, n = i & (N_NODES - 1);
            int local = g_pref[i] - g_pref[r << 15];
            g_rows[(r << 15) + local] = n;   // ascending in n per relation
            g_cmap[i] = local;
        }
    }
}

// ---------------- fp16 hi of x ----------------
__global__ void k_splitA(const float4* __restrict__ in) {
    int i = blockIdx.x * blockDim.x + threadIdx.x;
    float4 v = in[i];
    ((__half2*)g_Ahi)[2 * i]     = __half2(__float2half(v.x), __float2half(v.y));
    ((__half2*)g_Ahi)[2 * i + 1] = __half2(__float2half(v.z), __float2half(v.w));
}

// ---------------- transpose W (hi only) -> Bt [r][n][d] ----------------
__global__ void k_splitW(const float* __restrict__ W) {
    __shared__ float tile[32][33];
    int r = blockIdx.z, d0 = blockIdx.y * 32, f0 = blockIdx.x * 32;
    int tx = threadIdx.x, ty = threadIdx.y;
    const float* Wr = W + (size_t)r * DIM * DIM;
#pragma unroll
    for (int j = 0; j < 32; j += 8)
        tile[ty + j][tx] = Wr[(size_t)(d0 + ty + j) * DIM + f0 + tx];
    __syncthreads();
#pragma unroll
    for (int j = 0; j < 32; j += 8) {
        int n = f0 + ty + j, d = d0 + tx;
        g_Bthi[((size_t)r * DIM + n) * DIM + d] = __float2half(tile[tx][ty + j]);
    }
}

// ---------------- Wqk[r][j][d] = (W_r @ [q|k]) transposed ----------------
template <int H>
__global__ void k_wqk(const float* __restrict__ W, const float* __restrict__ q,
                      const float* __restrict__ k) {
    int gw = (blockIdx.x * blockDim.x + threadIdx.x) >> 5;
    int lane = threadIdx.x & 31;
    if (gw >= N_REL * DIM) return;
    int r = gw / DIM, d = gw % DIM;
    const float* Wrow = W + ((size_t)r * DIM + d) * DIM;
    float acc[2 * H];
#pragma unroll
    for (int j = 0; j < 2 * H; j++) acc[j] = 0.f;
    for (int f = lane; f < DIM; f += 32) {
        float w = Wrow[f];
#pragma unroll
        for (int h = 0; h < H; h++) {
            acc[h]     = fmaf(w, __ldg(&q[f * H + h]), acc[h]);
            acc[H + h] = fmaf(w, __ldg(&k[f * H + h]), acc[H + h]);
        }
    }
#pragma unroll
    for (int j = 0; j < 2 * H; j++)
#pragma unroll
        for (int s = 16; s; s >>= 1) acc[j] += __shfl_xor_sync(0xffffffffu, acc[j], s);
    if (lane == 0) {
#pragma unroll
        for (int j = 0; j < 2 * H; j++)
            g_Wqk[((size_t)r * 2 * H + j) * DIM + d] = acc[j];
    }
}

// ---------------- Q/K: smem-staged Wqk, 2 nodes per warp ----------------
template <int H, bool FROM_H>
__global__ __launch_bounds__(256) void k_qkx(const float4* __restrict__ xin) {
    constexpr int NJ = N_REL * 2 * H;
    extern __shared__ float sW[];
    const float4* sW4 = (const float4*)sW;

    int tid = threadIdx.x, lane = tid & 31, w = tid >> 5;
#pragma unroll 4
    for (int i = tid; i < NJ * (DIM / 4); i += 256)
        ((float4*)sW)[i] = ((const float4*)g_Wqk)[i];
    __syncthreads();

    int n0 = blockIdx.x * 16 + w * 2;
    float accA[NJ], accB[NJ];
#pragma unroll
    for (int j = 0; j < NJ; j++) { accA[j] = 0.f; accB[j] = 0.f; }

#pragma unroll
    for (int i = 0; i < DIM / 128; i++) {
        int c4 = i * 32 + lane;
        float4 xa, xb;
        if (FROM_H) {
            uint2 ha = *(const uint2*)(g_Ahi + (size_t)n0 * DIM + 4 * c4);
            uint2 la = *(const uint2*)(g_Alo + (size_t)n0 * DIM + 4 * c4);
            uint2 hb = *(const uint2*)(g_Ahi + (size_t)(n0 + 1) * DIM + 4 * c4);
            uint2 lb = *(const uint2*)(g_Alo + (size_t)(n0 + 1) * DIM + 4 * c4);
            __half2 ah0 = *reinterpret_cast<__half2*>(&ha.x);
            __half2 ah1 = *reinterpret_cast<__half2*>(&ha.y);
            __half2 al0 = *reinterpret_cast<__half2*>(&la.x);
            __half2 al1 = *reinterpret_cast<__half2*>(&la.y);
            xa = make_float4(__half2float(ah0.x) + __half2float(al0.x),
                             __half2float(ah0.y) + __half2float(al0.y),
                             __half2float(ah1.x) + __half2float(al1.x),
                             __half2float(ah1.y) + __half2float(al1.y));
            __half2 bh0 = *reinterpret_cast<__half2*>(&hb.x);
            __half2 bh1 = *reinterpret_cast<__half2*>(&hb.y);
            __half2 bl0 = *reinterpret_cast<__half2*>(&lb.x);
            __half2 bl1 = *reinterpret_cast<__half2*>(&lb.y);
            xb = make_float4(__half2float(bh0.x) + __half2float(bl0.x),
                             __half2float(bh0.y) + __half2float(bl0.y),
                             __half2float(bh1.x) + __half2float(bl1.x),
                             __half2float(bh1.y) + __half2float(bl1.y));
        } else {
            xa = xin[(size_t)n0 * (DIM / 4) + c4];
            xb = xin[(size_t)(n0 + 1) * (DIM / 4) + c4];
        }
#pragma unroll
        for (int j = 0; j < NJ; j++) {
            float4 wv = sW4[j * (DIM / 4) + c4];
            accA[j] = fmaf(xa.x, wv.x, fmaf(xa.y, wv.y, fmaf(xa.z, wv.z, fmaf(xa.w, wv.w, accA[j]))));
            accB[j] = fmaf(xb.x, wv.x, fmaf(xb.y, wv.y, fmaf(xb.z, wv.z, fmaf(xb.w, wv.w, accB[j]))));
        }
    }
#pragma unroll
    for (int j = 0; j < NJ; j++) {
#pragma unroll
        for (int s = 16; s; s >>= 1) {
            accA[j] += __shfl_xor_sync(0xffffffffu, accA[j], s);
            accB[j] += __shfl_xor_sync(0xffffffffu, accB[j], s);
        }
    }
    if (lane < 2) {
        const float* acc = lane == 0 ? accA : accB;
        int n = n0 + lane;
#pragma unroll
        for (int r = 0; r < N_REL; r++)
#pragma unroll
            for (int h = 0; h < H; h++) {
                g_Q[(r * N_NODES + n) * H + h] = acc[r * 2 * H + h];
                g_K[(r * N_NODES + n) * H + h] = acc[r * 2 * H + H + h];
            }
    }
}

// ---------------- HMMA GEMM (single-product fp16, row-range predicated) -------------
__device__ __forceinline__ void load_chunk(unsigned stg, int k0, const int* sR,
        const __half* bH, int t) {
#pragma unroll
    for (int p = 0; p < 4; p++) {
        int u = p * 256 + t;
        int row = u >> 3, kc = u & 7;
        unsigned off = sw128(row * 128 + kc * 16);
        cp16(stg + ST_A + off, g_Ahi + (size_t)sR[row] * DIM + k0 + kc * 8);
        cp16(stg + ST_B + off, bH + (size_t)row * DIM + k0 + kc * 8);
    }
}

__global__ __launch_bounds__(256, 2) void k_gemm_mma(int loLim, int hiLim) {
    extern __shared__ char smem[];
    __shared__ int sRows[MT];
    unsigned sb = smem_u32(smem);
    int t = threadIdx.x, wid = t >> 5, lane = t & 31;
    int wm = wid & 1, wn = wid >> 1;
    int nt6 = blockIdx.x % 6, r = blockIdx.x / 6;
    int bm = blockIdx.y * MT, bn = nt6 * NT;

    int cnt = g_rcnt[r];
    if (bm >= cnt) return;
    if (t < MT) sRows[t] = (bm + t < cnt) ? g_rows[(r << 15) + bm + t] : 0;
    __syncthreads();   // sRows visible

    // tile's max node row (rows ascending); uniform predicate
    int last = (cnt - bm >= MT) ? MT - 1 : cnt - bm - 1;
    int mx = sRows[last];
    if (mx < loLim || mx >= hiLim) return;

    const __half* bH = g_Bthi + ((size_t)r * DIM + bn) * DIM;

    float acc[4][4][4];
#pragma unroll
    for (int i = 0; i < 4; i++)
#pragma unroll
        for (int j = 0; j < 4; j++)
#pragma unroll
            for (int k = 0; k < 4; k++) acc[i][j][k] = 0.f;

    unsigned aRowB = (unsigned)(wm * 64 + (lane & 15)) * 128;
    unsigned aColB = (unsigned)(lane >> 4) * 16;
    unsigned bRowB = (unsigned)(wn * 32 + (lane & 7) + ((lane >> 4) << 3)) * 128;
    unsigned bColB = (unsigned)((lane >> 3) & 1) * 16;

#pragma unroll
    for (int s = 0; s < NSTAGE - 1; s++) {
        load_chunk(sb + s * STAGE_SZ, s * KC, sRows, bH, t);
        asm volatile("cp.async.commit_group;" ::: "memory");
    }

    for (int i = 0; i < NCHUNK; i++) {
        asm volatile("cp.async.wait_group %0;" :: "n"(NSTAGE - 2) : "memory");
        __syncthreads();

        if (i + NSTAGE - 1 < NCHUNK) {
            load_chunk(sb + ((i + NSTAGE - 1) % NSTAGE) * STAGE_SZ,
                       (i + NSTAGE - 1) * KC, sRows, bH, t);
        }
        asm volatile("cp.async.commit_group;" ::: "memory");

        unsigned stg = sb + (unsigned)(i % NSTAGE) * STAGE_SZ;
#pragma unroll
        for (int ks = 0; ks < 4; ks++) {
            unsigned bHi[2][4];
#pragma unroll
            for (int nb = 0; nb < 2; nb++)
                ldsm4(bHi[nb], stg + ST_B + sw128(bRowB + nb * 2048 + bColB + ks * 32));
#pragma unroll
            for (int mt = 0; mt < 4; mt++) {
                unsigned aHi[4];
                ldsm4(aHi, stg + ST_A + sw128(aRowB + mt * 2048 + aColB + ks * 32));
#pragma unroll
                for (int nb = 0; nb < 2; nb++)
#pragma unroll
                    for (int half = 0; half < 2; half++) {
                        int nt = nb * 2 + half, rg = half * 2;
                        mma16816(acc[mt][nt], aHi, &bHi[nb][rg]);
                    }
            }
        }
    }

    __half* C = g_xr + ((size_t)r * N_NODES + bm) * DIM + bn;
#pragma unroll
    for (int mt = 0; mt < 4; mt++)
#pragma unroll
        for (int nt = 0; nt < 4; nt++) {
            int row = wm * 64 + mt * 16 + (lane >> 2);
            int col = wn * 32 + nt * 8 + (lane & 3) * 2;
            *(__half2*)(C + (size_t)row * DIM + col) =
                __floats2half2_rn(acc[mt][nt][0], acc[mt][nt][1]);
            *(__half2*)(C + (size_t)(row + 8) * DIM + col) =
                __floats2half2_rn(acc[mt][nt][2], acc[mt][nt][3]);
        }
}

// ---------------- per-edge attention logits ----------------
template <int H>
__global__ void k_alpha() {
    int e = blockIdx.x * blockDim.x + threadIdx.x;
    if (e >= N_EDGES) return;
    int et = g_et[e], s = g_src[e], d = g_dst[e];
    int bq = (et * N_NODES + d) * H;
    int bk = (et * N_NODES + s) * H;
#pragma unroll
    for (int h = 0; h < H; h++) {
        float v = g_Q[bq + h] + g_K[bk + h];
        g_alpha[e * H + h] = (v >= 0.f) ? v : 0.2f * v;
    }
}

// ---------------- per-node segment softmax + aggregation (fp16 xr gather) ------------
template <int H, int OUT, bool ELU, bool SPLIT>
__global__ __launch_bounds__(128) void k_agg(const float* __restrict__ bias,
                                             float* __restrict__ outp, int nbase) {
    int n = nbase + blockIdx.x;
    int off = g_off[n];
    int cnt = g_off[n + 1] - off;

    __shared__ float sm_m[H], sm_rz[H];
    __shared__ int   sm_row[128];
    __shared__ float sm_a[128 * H];

    int tid = threadIdx.x, lane = tid & 31, w = tid >> 5;

    if (w < H) {
        float mx = -3.0e38f;
        for (int i = lane; i < cnt; i += 32) {
            int e = g_eperm[off + i];
            mx = fmaxf(mx, g_alpha[e * H + w]);
        }
#pragma unroll
        for (int s = 16; s; s >>= 1) mx = fmaxf(mx, __shfl_xor_sync(0xffffffffu, mx, s));
        float z = 0.f;
        for (int i = lane; i < cnt; i += 32) {
            int e = g_eperm[off + i];
            z += expf(g_alpha[e * H + w] - mx);
        }
#pragma unroll
        for (int s = 16; s; s >>= 1) z += __shfl_xor_sync(0xffffffffu, z, s);
        if (lane == 0) { sm_m[w] = mx; sm_rz[w] = 1.f / (z + 1e-16f); }
    }
    __syncthreads();

    float acc[3][2] = {{0.f,0.f},{0.f,0.f},{0.f,0.f}};
    int hidx[3];
#pragma unroll
    for (int j = 0; j < 3; j++) hidx[j] = (2 * (tid + j * 128)) / OUT;

    const __half2* xr2 = (const __half2*)g_xr;
    for (int base = 0; base < cnt; base += 128) {
        int c = cnt - base;
        if (c > 128) c = 128;
        if (tid < c) {
            int e = g_eperm[off + base + tid];
            int r = g_et[e];
            sm_row[tid] = (r * N_NODES + g_cmap[(r << 15) + g_src[e]]) * (DIM / 2);
#pragma unroll
            for (int h = 0; h < H; h++)
                sm_a[tid * H + h] = expf(g_alpha[e * H + h] - sm_m[h]) * sm_rz[h];
        }
        __syncthreads();
        for (int i = 0; i < c; i++) {
            const __half2* row = xr2 + sm_row[i];
#pragma unroll
            for (int j = 0; j < 3; j++) {
                float a = sm_a[i * H + hidx[j]];
                __half2 hv = row[tid + j * 128];
                acc[j][0] = fmaf(a, __low2float(hv), acc[j][0]);
                acc[j][1] = fmaf(a, __high2float(hv), acc[j][1]);
            }
        }
        __syncthreads();
    }

    size_t ob = (size_t)n * DIM;
#pragma unroll
    for (int j = 0; j < 3; j++) {
        int cch = 2 * (tid + j * 128);
        float v0 = acc[j][0] + bias[cch];
        float v1 = acc[j][1] + bias[cch + 1];
        if (ELU) {
            v0 = (v0 > 0.f) ? v0 : expm1f(v0);
            v1 = (v1 > 0.f) ? v1 : expm1f(v1);
        }
        if (SPLIT) {
            __half h0 = __float2half(v0), h1 = __float2half(v1);
            g_Ahi[ob + cch]     = h0;
            g_Ahi[ob + cch + 1] = h1;
            g_Alo[ob + cch]     = __float2half(v0 - __half2float(h0));
            g_Alo[ob + cch + 1] = __float2half(v1 - __half2float(h1));
        } else {
            outp[ob + cch]     = v0;
            outp[ob + cch + 1] = v1;
        }
    }
}

// ---------------- launch ----------------
extern "C" void kernel_launch(void* const* d_in, const int* in_sizes, int n_in,
                              void* d_out, int out_size) {
    const float* x  = (const float*)d_in[0];
    const int*   ei = (const int*)d_in[1];
    const int*   et = (const int*)d_in[2];
    const float* W1 = (const float*)d_in[3];
    const float* q1 = (const float*)d_in[4];
    const float* k1 = (const float*)d_in[5];
    const float* b1 = (const float*)d_in[6];
    const float* W2 = (const float*)d_in[7];
    const float* q2 = (const float*)d_in[8];
    const float* k2 = (const float*)d_in[9];
    const float* b2 = (const float*)d_in[10];
    float* out = (float*)d_out;

    const int QK1_SMEM = N_REL * 2 * H1 * DIM * 4;
    const int QK2_SMEM = N_REL * 2 * H2 * DIM * 4;
    cudaFuncSetAttribute(k_gemm_mma, cudaFuncAttributeMaxDynamicSharedMemorySize, SMEM_TOTAL);
    cudaFuncSetAttribute(k_qkx<H1, false>, cudaFuncAttributeMaxDynamicSharedMemorySize, QK1_SMEM);
    cudaFuncSetAttribute(k_qkx<H2, true>,  cudaFuncAttributeMaxDynamicSharedMemorySize, QK2_SMEM);

    cudaStream_t s2 = g_sp.s2, s3 = g_sp.s3;
    dim3 ggrid(6 * N_REL, N_NODES / MT);
    dim3 wgrid(DIM / 32, DIM / 32, N_REL);
    dim3 wblk(32, 8);
    int  ablocks = (N_NODES * DIM / 4) / 256;

    // ---- fork helper streams from the capture-origin stream FIRST ----
    cudaEventRecord(g_sp.evFork, 0);
    cudaStreamWaitEvent(s2, g_sp.evFork, 0);
    cudaStreamWaitEvent(s3, g_sp.evFork, 0);

    // main: GEMM-1 inputs
    k_splitA<<<ablocks, 256>>>((const float4*)x);                  // 1
    k_splitW<<<wgrid, wblk>>>(W1);                                 // 2

    // s3: layer-1 Q/K path
    k_wqk<H1><<<(N_REL * DIM) / 8, 256, 0, s3>>>(W1, q1, k1);      // 3
    k_qkx<H1, false><<<N_NODES / 16, 256, QK1_SMEM, s3>>>((const float4*)x);  // 4

    // s2: fused CSR + compaction
    k_zero2<<<(N_REL * N_NODES + 255) / 256, 256, 0, s2>>>();
    k_prep2<<<(N_EDGES + 255) / 256, 256, 0, s2>>>(ei, et);
    k_scan2<<<2, 1024, 0, s2>>>();
    k_scat2<<<SCAT_BLKS + RSC_BLKS, 256, 0, s2>>>();
    cudaEventRecord(g_sp.evCSR, s2);

    // s3: alpha1 — hides under gemm1
    cudaStreamWaitEvent(s3, g_sp.evCSR, 0);
    k_alpha<H1><<<(N_EDGES + 255) / 256, 256, 0, s3>>>();
    cudaEventRecord(g_sp.evQA1, s3);

    // main: gemm1 (all tiles)
    cudaStreamWaitEvent(0, g_sp.evCSR, 0);
    k_gemm_mma<<<ggrid, 256, SMEM_TOTAL>>>(0, N_NODES);
    cudaEventRecord(g_sp.evG1, 0);

    // s2: layer-2 weight prep — hides under agg1
    cudaStreamWaitEvent(s2, g_sp.evG1, 0);
    k_splitW<<<wgrid, wblk, 0, s2>>>(W2);
    k_wqk<H2><<<(N_REL * DIM) / 8, 256, 0, s2>>>(W2, q2, k2);
    cudaEventRecord(g_sp.evW2, s2);

    // main: agg1a (nodes [0, HALFN)) — needs gemm1 (main order) + alpha1
    cudaStreamWaitEvent(0, g_sp.evQA1, 0);
    k_agg<H1, O1, true, true><<<HALFN, 128>>>(b1, nullptr, 0);
    cudaEventRecord(g_sp.evA1a, 0);

    // s2: agg1b (nodes [HALFN, N)) — concurrent with gemm2 phase 1
    cudaStreamWaitEvent(s2, g_sp.evQA1, 0);
    k_agg<H1, O1, true, true><<<HALFN, 128, 0, s2>>>(b1, nullptr, HALFN);
    cudaEventRecord(g_sp.evA1b, 0 /*dummy*/), cudaEventRecord(g_sp.evA1b, s2);

    // main: gemm2 phase 1 (tiles with maxRow < HALFN) — needs agg1a + W2
    cudaStreamWaitEvent(0, g_sp.evW2, 0);
    k_gemm_mma<<<ggrid, 256, SMEM_TOTAL>>>(0, HALFN);

    // s3: qkx2 + alpha2 — needs all h + wqk2; hides under gemm2 phase 2
    cudaStreamWaitEvent(s3, g_sp.evA1a, 0);
    cudaStreamWaitEvent(s3, g_sp.evA1b, 0);
    cudaStreamWaitEvent(s3, g_sp.evW2, 0);
    k_qkx<H2, true><<<N_NODES / 16, 256, QK2_SMEM, s3>>>(nullptr);
    k_alpha<H2><<<(N_EDGES + 255) / 256, 256, 0, s3>>>();
    cudaEventRecord(g_sp.evJ2, s3);

    // main: gemm2 phase 2 (tiles with maxRow >= HALFN) — needs agg1b
    cudaStreamWaitEvent(0, g_sp.evA1b, 0);
    k_gemm_mma<<<ggrid, 256, SMEM_TOTAL>>>(HALFN, N_NODES);

    // main: agg2 (full)
    cudaStreamWaitEvent(0, g_sp.evJ2, 0);
    k_agg<H2, O2, false, false><<<N_NODES, 128>>>(b2, out, 0);
}